// round 2
// baseline (speedup 1.0000x reference)
#include <cuda_runtime.h>
#include <cuda_bf16.h>
#include <math.h>

// Problem constants (from reference setup_inputs): B=8, N=2048, D=256
#define BATCH 8
#define NN 2048
#define DD 256

// GEMM tiling
#define BM 128
#define BN 128
#define BK 16
#define TM 8
#define TN 8
#define NTILES 16              // NN / BM
#define NTRI 136               // NTILES*(NTILES+1)/2 upper-triangular tiles

// ---------------------------------------------------------------------------
// Kernel 1: energy = h @ h^T (symmetric) -> out used as scratch for energy.
// Upper-triangular tile grid; mirror-write the transposed block when off-diag.
// ---------------------------------------------------------------------------
__global__ __launch_bounds__(256, 2)
void energy_gemm_kernel(const float* __restrict__ h, float* __restrict__ out) {
    const int b = blockIdx.y;
    const int idx = blockIdx.x;   // 0..NTRI-1, linear index into upper triangle

    // closed-form map: idx -> (ti, tj), tj >= ti, row-major over the triangle
    // ti = NTILES - 1 - floor((sqrt(8*(NTRI-1-idx)+1)-1)/2)
    const int rev = NTRI - 1 - idx;
    const int rrow = (int)((sqrtf(8.0f * (float)rev + 1.0f) - 1.0f) * 0.5f);
    const int ti = NTILES - 1 - rrow;
    const int tj = NTILES - 1 - (rev - (rrow * (rrow + 1)) / 2) ;

    const float* __restrict__ hb = h + (size_t)b * NN * DD;
    float* __restrict__ ob = out + (size_t)b * NN * NN;

    __shared__ float As[BK][BM];
    __shared__ float Bs[BK][BN];

    const int tid = threadIdx.x;          // 0..255
    const int tx = tid & 15;              // col group
    const int ty = tid >> 4;              // row group

    float acc[TM][TN];
#pragma unroll
    for (int i = 0; i < TM; i++)
#pragma unroll
        for (int j = 0; j < TN; j++) acc[i][j] = 0.0f;

    const float* __restrict__ Abase = hb + (size_t)(ti * BM) * DD;
    const float* __restrict__ Bbase = hb + (size_t)(tj * BN) * DD;

#pragma unroll
    for (int k0 = 0; k0 < DD; k0 += BK) {
        // Load 128x16 A and B tiles: 512 float4 each, 2 per thread.
#pragma unroll
        for (int q = 0; q < 2; q++) {
            const int f  = tid * 2 + q;      // 0..511
            const int r  = f >> 2;           // row 0..127
            const int c4 = (f & 3) * 4;      // 0,4,8,12
            float4 va = *(const float4*)(Abase + (size_t)r * DD + k0 + c4);
            As[c4 + 0][r] = va.x; As[c4 + 1][r] = va.y;
            As[c4 + 2][r] = va.z; As[c4 + 3][r] = va.w;
            float4 vb = *(const float4*)(Bbase + (size_t)r * DD + k0 + c4);
            Bs[c4 + 0][r] = vb.x; Bs[c4 + 1][r] = vb.y;
            Bs[c4 + 2][r] = vb.z; Bs[c4 + 3][r] = vb.w;
        }
        __syncthreads();

#pragma unroll
        for (int k = 0; k < BK; k++) {
            float a[TM], bb[TN];
            *(float4*)&a[0]  = *(const float4*)&As[k][ty * TM];
            *(float4*)&a[4]  = *(const float4*)&As[k][ty * TM + 4];
            *(float4*)&bb[0] = *(const float4*)&Bs[k][tx * TN];
            *(float4*)&bb[4] = *(const float4*)&Bs[k][tx * TN + 4];
#pragma unroll
            for (int i = 0; i < TM; i++)
#pragma unroll
                for (int j = 0; j < TN; j++)
                    acc[i][j] = fmaf(a[i], bb[j], acc[i][j]);
        }
        __syncthreads();
    }

    const int rbase = ti * BM + ty * TM;
    const int cbase = tj * BN + tx * TN;

    // direct block write (coalesced)
#pragma unroll
    for (int i = 0; i < TM; i++) {
        float* p = ob + (size_t)(rbase + i) * NN + cbase;
        *(float4*)(p)     = make_float4(acc[i][0], acc[i][1], acc[i][2], acc[i][3]);
        *(float4*)(p + 4) = make_float4(acc[i][4], acc[i][5], acc[i][6], acc[i][7]);
    }

    // mirrored (transposed) block for the lower triangle
    if (ti != tj) {
#pragma unroll
        for (int j = 0; j < TN; j++) {
            float* p = ob + (size_t)(cbase + j) * NN + rbase;
            *(float4*)(p)     = make_float4(acc[0][j], acc[1][j], acc[2][j], acc[3][j]);
            *(float4*)(p + 4) = make_float4(acc[4][j], acc[5][j], acc[6][j], acc[7][j]);
        }
    }
}

// ---------------------------------------------------------------------------
// Kernel 2: per-row  t = (rowmax(e) - e) * adj;  out = softmax(t)
// One CTA (256 threads) per row; e held in registers (8/thread), 3 block reds.
// ---------------------------------------------------------------------------
__device__ __forceinline__ float warp_max(float v) {
#pragma unroll
    for (int o = 16; o > 0; o >>= 1)
        v = fmaxf(v, __shfl_xor_sync(0xFFFFFFFFu, v, o));
    return v;
}
__device__ __forceinline__ float warp_sum(float v) {
#pragma unroll
    for (int o = 16; o > 0; o >>= 1)
        v += __shfl_xor_sync(0xFFFFFFFFu, v, o);
    return v;
}

__global__ __launch_bounds__(256, 8)
void softmax_adj_kernel(float* __restrict__ out, const float* __restrict__ adj) {
    const size_t row = blockIdx.x;                      // 0 .. B*NN-1
    float* __restrict__ e = out + row * NN;
    const float* __restrict__ a = adj + row * NN;

    __shared__ float red[8];
    const int tid  = threadIdx.x;
    const int lane = tid & 31;
    const int wid  = tid >> 5;

    // load 8 energy values per thread (two coalesced float4 sweeps)
    float4 e0 = ((const float4*)e)[tid];
    float4 e1 = ((const float4*)e)[tid + 256];

    // ---- reduction 1: M = rowmax(e)
    float m = fmaxf(fmaxf(fmaxf(e0.x, e0.y), fmaxf(e0.z, e0.w)),
                    fmaxf(fmaxf(e1.x, e1.y), fmaxf(e1.z, e1.w)));
    m = warp_max(m);
    if (lane == 0) red[wid] = m;
    __syncthreads();
    if (wid == 0) {
        float v = red[lane & 7];
        v = fmaxf(v, __shfl_xor_sync(0xFFFFFFFFu, v, 4));
        v = fmaxf(v, __shfl_xor_sync(0xFFFFFFFFu, v, 2));
        v = fmaxf(v, __shfl_xor_sync(0xFFFFFFFFu, v, 1));
        if (lane == 0) red[0] = v;
    }
    __syncthreads();
    const float M = red[0];
    __syncthreads();

    // ---- t = (M - e) * adj ; reduction 2: T = rowmax(t)
    float4 a0 = ((const float4*)a)[tid];
    float4 a1 = ((const float4*)a)[tid + 256];

    float t[8];
    t[0] = (M - e0.x) * a0.x;  t[1] = (M - e0.y) * a0.y;
    t[2] = (M - e0.z) * a0.z;  t[3] = (M - e0.w) * a0.w;
    t[4] = (M - e1.x) * a1.x;  t[5] = (M - e1.y) * a1.y;
    t[6] = (M - e1.z) * a1.z;  t[7] = (M - e1.w) * a1.w;

    float tm = t[0];
#pragma unroll
    for (int k = 1; k < 8; k++) tm = fmaxf(tm, t[k]);
    tm = warp_max(tm);
    if (lane == 0) red[wid] = tm;
    __syncthreads();
    if (wid == 0) {
        float v = red[lane & 7];
        v = fmaxf(v, __shfl_xor_sync(0xFFFFFFFFu, v, 4));
        v = fmaxf(v, __shfl_xor_sync(0xFFFFFFFFu, v, 2));
        v = fmaxf(v, __shfl_xor_sync(0xFFFFFFFFu, v, 1));
        if (lane == 0) red[0] = v;
    }
    __syncthreads();
    const float T = red[0];
    __syncthreads();

    // ---- p = exp(t - T); reduction 3: S = sum(p)
    float p[8];
    float s = 0.0f;
#pragma unroll
    for (int k = 0; k < 8; k++) {
        p[k] = __expf(t[k] - T);
        s += p[k];
    }
    s = warp_sum(s);
    if (lane == 0) red[wid] = s;
    __syncthreads();
    if (wid == 0) {
        float v = red[lane & 7];
        v += __shfl_xor_sync(0xFFFFFFFFu, v, 4);
        v += __shfl_xor_sync(0xFFFFFFFFu, v, 2);
        v += __shfl_xor_sync(0xFFFFFFFFu, v, 1);
        if (lane == 0) red[0] = v;
    }
    __syncthreads();
    const float inv = 1.0f / red[0];

    // ---- write normalized attention
    float4 o0 = make_float4(p[0] * inv, p[1] * inv, p[2] * inv, p[3] * inv);
    float4 o1 = make_float4(p[4] * inv, p[5] * inv, p[6] * inv, p[7] * inv);
    ((float4*)e)[tid]       = o0;
    ((float4*)e)[tid + 256] = o1;
}

// ---------------------------------------------------------------------------
extern "C" void kernel_launch(void* const* d_in, const int* in_sizes, int n_in,
                              void* d_out, int out_size) {
    const float* h   = (const float*)d_in[0];   // [B, N, D]
    const float* adj = (const float*)d_in[1];   // [B, N, N]
    float* out = (float*)d_out;                 // [B, N, N]

    dim3 ggrid(NTRI, BATCH);
    energy_gemm_kernel<<<ggrid, 256>>>(h, out);

    softmax_adj_kernel<<<BATCH * NN, 256>>>(out, adj);
}

// round 4
// speedup vs baseline: 1.4381x; 1.4381x over previous
#include <cuda_runtime.h>
#include <cuda_bf16.h>
#include <cstdint>
#include <math.h>

// Problem constants: B=8, N=2048, D=256
#define BATCH 8
#define NN 2048
#define DD 256

#define TILE 128
#define NTILES 16              // NN / TILE
#define NTRI 136               // NTILES*(NTILES+1)/2

#define BK 32                  // K chunk
#define NCHUNK (DD / BK)       // 8
#define PAD 36                 // padded row stride (floats) for smem tiles
#define TILE_F (TILE * PAD)    // floats per smem buffer (4608)
#define TILE_B (TILE_F * 4)    // bytes per smem buffer (18432)
#define SMEM_DYN (TILE_B * 8)  // 2 stages x 4 buffers = 147456 B

// ---------------------------------------------------------------------------
// tf32 split operands (device globals; no runtime allocation allowed)
// stored as fp32 bit patterns already rounded to tf32 (cvt.rna)
// ---------------------------------------------------------------------------
__device__ float g_hi[BATCH * NN * DD];
__device__ float g_lo[BATCH * NN * DD];

// ---------------------------------------------------------------------------
// helpers
// ---------------------------------------------------------------------------
__device__ __forceinline__ uint32_t smem_u32(const void* p) {
    uint32_t a;
    asm("{ .reg .u64 t; cvta.to.shared.u64 t, %1; cvt.u32.u64 %0, t; }" : "=r"(a) : "l"(p));
    return a;
}

#define CP_ASYNC16(dst, src) \
    asm volatile("cp.async.cg.shared.global [%0], [%1], 16;" :: "r"(dst), "l"(src))
#define CP_COMMIT() asm volatile("cp.async.commit_group;")
#define CP_WAIT(n)  asm volatile("cp.async.wait_group %0;" :: "n"(n))

#define MMA_TF32(c, a, b) \
    asm volatile("mma.sync.aligned.m16n8k8.row.col.f32.tf32.tf32.f32 " \
        "{%0,%1,%2,%3}, {%4,%5,%6,%7}, {%8,%9}, {%0,%1,%2,%3};" \
        : "+f"((c)[0]), "+f"((c)[1]), "+f"((c)[2]), "+f"((c)[3]) \
        : "r"((a)[0]), "r"((a)[1]), "r"((a)[2]), "r"((a)[3]), \
          "r"((b)[0]), "r"((b)[1]))

__device__ __forceinline__ uint32_t f2u(float x) { return __float_as_uint(x); }

// ---------------------------------------------------------------------------
// Kernel 0: split h (fp32) into tf32 hi + lo
// ---------------------------------------------------------------------------
__global__ __launch_bounds__(256)
void split_kernel(const float* __restrict__ h) {
    const size_t i = ((size_t)blockIdx.x * 256 + threadIdx.x) * 4;
    float4 v = *(const float4*)(h + i);
    float x[4] = { v.x, v.y, v.z, v.w };
    uint32_t hi[4], lo[4];
#pragma unroll
    for (int k = 0; k < 4; k++) {
        asm("cvt.rna.tf32.f32 %0, %1;" : "=r"(hi[k]) : "f"(x[k]));
        float r = x[k] - __uint_as_float(hi[k]);
        asm("cvt.rna.tf32.f32 %0, %1;" : "=r"(lo[k]) : "f"(r));
    }
    *(uint4*)(g_hi + i) = make_uint4(hi[0], hi[1], hi[2], hi[3]);
    *(uint4*)(g_lo + i) = make_uint4(lo[0], lo[1], lo[2], lo[3]);
}

// ---------------------------------------------------------------------------
// Kernel 1: energy = h @ h^T via 3xTF32 mma.sync, symmetric tiles.
// ---------------------------------------------------------------------------
// load one 128x32 fp32 tile (global row stride DD) into padded smem buffer
__device__ __forceinline__ void cp_tile(uint32_t dst, const float* __restrict__ src, int tid) {
#pragma unroll
    for (int q = 0; q < 4; q++) {
        const int idx = tid + q * 256;   // 0..1023
        const int row = idx >> 3;        // 0..127
        const int seg = idx & 7;         // 0..7 (4 floats each)
        CP_ASYNC16(dst + (uint32_t)(row * PAD + seg * 4) * 4,
                   src + (size_t)row * DD + seg * 4);
    }
}

__global__ __launch_bounds__(256, 1)
void energy_tc_kernel(float* __restrict__ out) {
    extern __shared__ float smem[];
    const uint32_t sb = smem_u32(smem);
    const int tid  = threadIdx.x;
    const int wid  = tid >> 5;
    const int lane = tid & 31;
    const int wm = wid & 1;          // 2 row blocks of 64
    const int wn = wid >> 1;         // 4 col blocks of 32

    const int b = blockIdx.y;
    const int idx = blockIdx.x;
    const int rev = NTRI - 1 - idx;
    const int rrow = (int)((sqrtf(8.0f * (float)rev + 1.0f) - 1.0f) * 0.5f);
    const int ti = NTILES - 1 - rrow;
    const int tj = NTILES - 1 - (rev - (rrow * (rrow + 1)) / 2);
    const bool diag = (ti == tj);

    const float* Ahi = g_hi + ((size_t)b * NN + (size_t)ti * TILE) * DD;
    const float* Alo = g_lo + ((size_t)b * NN + (size_t)ti * TILE) * DD;
    const float* Bhi = g_hi + ((size_t)b * NN + (size_t)tj * TILE) * DD;
    const float* Blo = g_lo + ((size_t)b * NN + (size_t)tj * TILE) * DD;

    float acc[16][4];
#pragma unroll
    for (int f = 0; f < 16; f++)
#pragma unroll
        for (int c = 0; c < 4; c++) acc[f][c] = 0.0f;

    // per-thread fragment coordinates
    const int gq = lane >> 2;     // group id 0..7
    const int tg = lane & 3;      // thread in group 0..3
    const int a_row = wm * 64 + gq;
    const int b_n   = wn * 32 + gq;

    // stage buffer base addresses (bytes)
    auto buf = [&](int stage, int which) -> uint32_t {
        return sb + (uint32_t)(stage * 4 + which) * TILE_B;
    };
    auto prefetch = [&](int chunk, int stage) {
        const int k0 = chunk * BK;
        cp_tile(buf(stage, 0), Ahi + k0, tid);
        cp_tile(buf(stage, 1), Alo + k0, tid);
        if (!diag) {
            cp_tile(buf(stage, 2), Bhi + k0, tid);
            cp_tile(buf(stage, 3), Blo + k0, tid);
        }
        CP_COMMIT();
    };

    prefetch(0, 0);

    for (int c = 0; c < NCHUNK; c++) {
        if (c + 1 < NCHUNK) prefetch(c + 1, (c + 1) & 1);
        if (c + 1 < NCHUNK) { CP_WAIT(1); } else { CP_WAIT(0); }
        __syncthreads();

        const int stage = c & 1;
        const float* Ah = smem + (size_t)(stage * 4 + 0) * TILE_F;
        const float* Al = smem + (size_t)(stage * 4 + 1) * TILE_F;
        const float* Bh = diag ? Ah : smem + (size_t)(stage * 4 + 2) * TILE_F;
        const float* Bl = diag ? Al : smem + (size_t)(stage * 4 + 3) * TILE_F;

#pragma unroll
        for (int ks = 0; ks < 4; ks++) {
            const int kb = ks * 8 + tg;
            uint32_t ah[4][4], al[4][4];
#pragma unroll
            for (int mf = 0; mf < 4; mf++) {
                const int r0 = (a_row + mf * 16) * PAD + kb;
                const int r1 = r0 + 8 * PAD;
                ah[mf][0] = f2u(Ah[r0]);     ah[mf][1] = f2u(Ah[r1]);
                ah[mf][2] = f2u(Ah[r0 + 4]); ah[mf][3] = f2u(Ah[r1 + 4]);
                al[mf][0] = f2u(Al[r0]);     al[mf][1] = f2u(Al[r1]);
                al[mf][2] = f2u(Al[r0 + 4]); al[mf][3] = f2u(Al[r1 + 4]);
            }
            uint32_t bh[4][2], bl[4][2];
#pragma unroll
            for (int nf = 0; nf < 4; nf++) {
                const int c0 = (b_n + nf * 8) * PAD + kb;
                bh[nf][0] = f2u(Bh[c0]); bh[nf][1] = f2u(Bh[c0 + 4]);
                bl[nf][0] = f2u(Bl[c0]); bl[nf][1] = f2u(Bl[c0 + 4]);
            }
#pragma unroll
            for (int mf = 0; mf < 4; mf++)
#pragma unroll
                for (int nf = 0; nf < 4; nf++) {
                    float* cc = acc[mf * 4 + nf];
                    MMA_TF32(cc, ah[mf], bh[nf]);   // hi*hi
                    MMA_TF32(cc, ah[mf], bl[nf]);   // hi*lo
                    MMA_TF32(cc, al[mf], bh[nf]);   // lo*hi
                }
        }
        __syncthreads();
    }

    // ---- epilogue: acc -> padded smem (128x129) -> coalesced global (tile + mirror)
    float* sf = smem;   // 128*129 floats = 66048 B, fits in stage-0 region
#pragma unroll
    for (int mf = 0; mf < 4; mf++)
#pragma unroll
        for (int nf = 0; nf < 4; nf++) {
            const int r0 = wm * 64 + mf * 16 + gq;
            const int c0 = wn * 32 + nf * 8 + tg * 2;
            const float* cc = acc[mf * 4 + nf];
            sf[r0 * 129 + c0]           = cc[0];
            sf[r0 * 129 + c0 + 1]       = cc[1];
            sf[(r0 + 8) * 129 + c0]     = cc[2];
            sf[(r0 + 8) * 129 + c0 + 1] = cc[3];
        }
    __syncthreads();

    float* __restrict__ ob = out + (size_t)b * NN * NN;
    const int rbase = ti * TILE;
    const int cbase = tj * TILE;

    for (int i2 = tid; i2 < 128 * 32; i2 += 256) {
        const int row = i2 >> 5;
        const int c4 = (i2 & 31) * 4;
        float4 v = make_float4(sf[row * 129 + c4], sf[row * 129 + c4 + 1],
                               sf[row * 129 + c4 + 2], sf[row * 129 + c4 + 3]);
        *(float4*)(ob + (size_t)(rbase + row) * NN + cbase + c4) = v;
    }
    if (!diag) {
        for (int i2 = tid; i2 < 128 * 32; i2 += 256) {
            const int mrow = i2 >> 5;
            const int c4 = (i2 & 31) * 4;
            float4 v = make_float4(sf[(c4 + 0) * 129 + mrow], sf[(c4 + 1) * 129 + mrow],
                                   sf[(c4 + 2) * 129 + mrow], sf[(c4 + 3) * 129 + mrow]);
            *(float4*)(ob + (size_t)(cbase + mrow) * NN + rbase + c4) = v;
        }
    }
}

// ---------------------------------------------------------------------------
// Kernel 2: per-row  t = (rowmax(e) - e) * adj;  out = softmax(t)  (unchanged)
// ---------------------------------------------------------------------------
__device__ __forceinline__ float warp_max(float v) {
#pragma unroll
    for (int o = 16; o > 0; o >>= 1) v = fmaxf(v, __shfl_xor_sync(0xFFFFFFFFu, v, o));
    return v;
}
__device__ __forceinline__ float warp_sum(float v) {
#pragma unroll
    for (int o = 16; o > 0; o >>= 1) v += __shfl_xor_sync(0xFFFFFFFFu, v, o);
    return v;
}

__global__ __launch_bounds__(256, 8)
void softmax_adj_kernel(float* __restrict__ out, const float* __restrict__ adj) {
    const size_t row = blockIdx.x;
    float* __restrict__ e = out + row * NN;
    const float* __restrict__ a = adj + row * NN;

    __shared__ float red[8];
    const int tid = threadIdx.x, lane = tid & 31, wid = tid >> 5;

    float4 e0 = ((const float4*)e)[tid];
    float4 e1 = ((const float4*)e)[tid + 256];

    float m = fmaxf(fmaxf(fmaxf(e0.x, e0.y), fmaxf(e0.z, e0.w)),
                    fmaxf(fmaxf(e1.x, e1.y), fmaxf(e1.z, e1.w)));
    m = warp_max(m);
    if (lane == 0) red[wid] = m;
    __syncthreads();
    if (wid == 0) {
        float v = red[lane & 7];
        v = fmaxf(v, __shfl_xor_sync(0xFFFFFFFFu, v, 4));
        v = fmaxf(v, __shfl_xor_sync(0xFFFFFFFFu, v, 2));
        v = fmaxf(v, __shfl_xor_sync(0xFFFFFFFFu, v, 1));
        if (lane == 0) red[0] = v;
    }
    __syncthreads();
    const float M = red[0];
    __syncthreads();

    float4 a0 = ((const float4*)a)[tid];
    float4 a1 = ((const float4*)a)[tid + 256];

    float t[8];
    t[0] = (M - e0.x) * a0.x;  t[1] = (M - e0.y) * a0.y;
    t[2] = (M - e0.z) * a0.z;  t[3] = (M - e0.w) * a0.w;
    t[4] = (M - e1.x) * a1.x;  t[5] = (M - e1.y) * a1.y;
    t[6] = (M - e1.z) * a1.z;  t[7] = (M - e1.w) * a1.w;

    float tm = t[0];
#pragma unroll
    for (int k = 1; k < 8; k++) tm = fmaxf(tm, t[k]);
    tm = warp_max(tm);
    if (lane == 0) red[wid] = tm;
    __syncthreads();
    if (wid == 0) {
        float v = red[lane & 7];
        v = fmaxf(v, __shfl_xor_sync(0xFFFFFFFFu, v, 4));
        v = fmaxf(v, __shfl_xor_sync(0xFFFFFFFFu, v, 2));
        v = fmaxf(v, __shfl_xor_sync(0xFFFFFFFFu, v, 1));
        if (lane == 0) red[0] = v;
    }
    __syncthreads();
    const float T = red[0];
    __syncthreads();

    float p[8], s = 0.0f;
#pragma unroll
    for (int k = 0; k < 8; k++) { p[k] = __expf(t[k] - T); s += p[k]; }
    s = warp_sum(s);
    if (lane == 0) red[wid] = s;
    __syncthreads();
    if (wid == 0) {
        float v = red[lane & 7];
        v += __shfl_xor_sync(0xFFFFFFFFu, v, 4);
        v += __shfl_xor_sync(0xFFFFFFFFu, v, 2);
        v += __shfl_xor_sync(0xFFFFFFFFu, v, 1);
        if (lane == 0) red[0] = v;
    }
    __syncthreads();
    const float inv = 1.0f / red[0];

    ((float4*)e)[tid]       = make_float4(p[0] * inv, p[1] * inv, p[2] * inv, p[3] * inv);
    ((float4*)e)[tid + 256] = make_float4(p[4] * inv, p[5] * inv, p[6] * inv, p[7] * inv);
}

// ---------------------------------------------------------------------------
extern "C" void kernel_launch(void* const* d_in, const int* in_sizes, int n_in,
                              void* d_out, int out_size) {
    const float* h   = (const float*)d_in[0];   // [B, N, D]
    const float* adj = (const float*)d_in[1];   // [B, N, N]
    float* out = (float*)d_out;                 // [B, N, N]

    cudaFuncSetAttribute(energy_tc_kernel, cudaFuncAttributeMaxDynamicSharedMemorySize, SMEM_DYN);

    split_kernel<<<(BATCH * NN * DD) / (256 * 4), 256>>>(h);

    dim3 ggrid(NTRI, BATCH);
    energy_tc_kernel<<<ggrid, 256, SMEM_DYN>>>(out);

    softmax_adj_kernel<<<BATCH * NN, 256>>>(out, adj);
}

// round 5
// speedup vs baseline: 2.1373x; 1.4862x over previous
#include <cuda_runtime.h>
#include <cuda_bf16.h>
#include <cstdint>
#include <math.h>

// Problem constants: B=8, N=2048, D=256
#define BATCH 8
#define NN 2048
#define DD 256

#define TILE 128
#define NTILES 16              // NN / TILE
#define NTRI 136               // NTILES*(NTILES+1)/2
#define NCHUNK 8               // K chunks of 32

// smem: per stage 4 regions x 8KB (Ahi, Alo, Bhi, Blo) = 32KB; 2 stages = 64KB
#define STAGE_B 32768
#define SMEM_DYN 66560         // >= 128*129*4 (epilogue) and >= 2*STAGE_B

// ---------------------------------------------------------------------------
// bf16 split operands in FRAGMENT-MAJOR layout (device globals)
// A-layout: [b][rb][chunk][kf][mf][thread 16B]   (m16n8k16 A fragments)
// B-layout: [b][rb][chunk][kf][nf][thread 8B]    (m16n8k16 B fragments)
// ---------------------------------------------------------------------------
__device__ __nv_bfloat16 gAhi[BATCH * NN * DD];
__device__ __nv_bfloat16 gAlo[BATCH * NN * DD];
__device__ __nv_bfloat16 gBhi[BATCH * NN * DD];
__device__ __nv_bfloat16 gBlo[BATCH * NN * DD];

// ---------------------------------------------------------------------------
// helpers
// ---------------------------------------------------------------------------
__device__ __forceinline__ uint32_t smem_u32(const void* p) {
    uint32_t a;
    asm("{ .reg .u64 t; cvta.to.shared.u64 t, %1; cvt.u32.u64 %0, t; }" : "=r"(a) : "l"(p));
    return a;
}
#define CP_ASYNC16(dst, src) \
    asm volatile("cp.async.cg.shared.global [%0], [%1], 16;" :: "r"(dst), "l"(src))
#define CP_COMMIT() asm volatile("cp.async.commit_group;")
#define CP_WAIT(n)  asm volatile("cp.async.wait_group %0;" :: "n"(n))

#define LDS_V4(r, addr) \
    asm volatile("ld.shared.v4.b32 {%0,%1,%2,%3}, [%4];" \
        : "=r"((r)[0]), "=r"((r)[1]), "=r"((r)[2]), "=r"((r)[3]) : "r"(addr))
#define LDS_V2(r, addr) \
    asm volatile("ld.shared.v2.b32 {%0,%1}, [%2];" \
        : "=r"((r)[0]), "=r"((r)[1]) : "r"(addr))

#define MMA_BF16(c, a, b) \
    asm volatile("mma.sync.aligned.m16n8k16.row.col.f32.bf16.bf16.f32 " \
        "{%0,%1,%2,%3}, {%4,%5,%6,%7}, {%8,%9}, {%0,%1,%2,%3};" \
        : "+f"((c)[0]), "+f"((c)[1]), "+f"((c)[2]), "+f"((c)[3]) \
        : "r"((a)[0]), "r"((a)[1]), "r"((a)[2]), "r"((a)[3]), \
          "r"((b)[0]), "r"((b)[1]))

__device__ __forceinline__ uint32_t pack_bf2(__nv_bfloat16 a, __nv_bfloat16 b) {
    return (uint32_t)__bfloat16_as_ushort(a) | ((uint32_t)__bfloat16_as_ushort(b) << 16);
}

// ---------------------------------------------------------------------------
// pack_a: h (fp32) -> gAhi/gAlo in m16n8k16 A-fragment-major layout
// slot s (16B = 8 bf16 = one thread's A fragment quarter):
//   t=s&31, mf=(s>>5)&7, kf=(s>>8)&1, chunk=(s>>9)&7, rb=(s>>12)&15, b=s>>16
// ---------------------------------------------------------------------------
__global__ __launch_bounds__(256)
void pack_a_kernel(const float* __restrict__ h) {
    const uint32_t s = blockIdx.x * 256 + threadIdx.x;      // 0..524287
    const int t = s & 31, mf = (s >> 5) & 7, kf = (s >> 8) & 1;
    const int chunk = (s >> 9) & 7, rb = (s >> 12) & 15, b = s >> 16;
    const int row = rb * 128 + mf * 16 + (t >> 2);
    const int kb  = chunk * 32 + kf * 16 + (t & 3) * 2;
    const float* base = h + ((size_t)(b * NN + row)) * DD + kb;
    float2 L00 = *(const float2*)(base);              // (gq,   2tg..2tg+1)
    float2 L10 = *(const float2*)(base + 8 * DD);     // (gq+8, 2tg..2tg+1)
    float2 L01 = *(const float2*)(base + 8);          // (gq,   2tg+8..+9)
    float2 L11 = *(const float2*)(base + 8 * DD + 8); // (gq+8, 2tg+8..+9)

    float x[8] = { L00.x, L00.y, L10.x, L10.y, L01.x, L01.y, L11.x, L11.y };
    __nv_bfloat16 hi[8], lo[8];
#pragma unroll
    for (int k = 0; k < 8; k++) {
        hi[k] = __float2bfloat16(x[k]);
        lo[k] = __float2bfloat16(x[k] - __bfloat162float(hi[k]));
    }
    uint4 vh = make_uint4(pack_bf2(hi[0], hi[1]), pack_bf2(hi[2], hi[3]),
                          pack_bf2(hi[4], hi[5]), pack_bf2(hi[6], hi[7]));
    uint4 vl = make_uint4(pack_bf2(lo[0], lo[1]), pack_bf2(lo[2], lo[3]),
                          pack_bf2(lo[4], lo[5]), pack_bf2(lo[6], lo[7]));
    ((uint4*)gAhi)[s] = vh;
    ((uint4*)gAlo)[s] = vl;
}

// ---------------------------------------------------------------------------
// pack_b: h (fp32) -> gBhi/gBlo in m16n8k16 B-fragment-major layout
// slot s (8B = 4 bf16):
//   t=s&31, nf=(s>>5)&15, kf=(s>>9)&1, chunk=(s>>10)&7, rb=(s>>13)&15, b=s>>17
// ---------------------------------------------------------------------------
__global__ __launch_bounds__(256)
void pack_b_kernel(const float* __restrict__ h) {
    const uint32_t s = blockIdx.x * 256 + threadIdx.x;      // 0..1048575
    const int t = s & 31, nf = (s >> 5) & 15, kf = (s >> 9) & 1;
    const int chunk = (s >> 10) & 7, rb = (s >> 13) & 15, b = s >> 17;
    const int n  = rb * 128 + nf * 8 + (t >> 2);
    const int kb = chunk * 32 + kf * 16 + (t & 3) * 2;
    const float* base = h + ((size_t)(b * NN + n)) * DD + kb;
    float2 K0 = *(const float2*)(base);       // k = 2tg, 2tg+1
    float2 K1 = *(const float2*)(base + 8);   // k = 2tg+8, 2tg+9

    float x[4] = { K0.x, K0.y, K1.x, K1.y };
    __nv_bfloat16 hi[4], lo[4];
#pragma unroll
    for (int k = 0; k < 4; k++) {
        hi[k] = __float2bfloat16(x[k]);
        lo[k] = __float2bfloat16(x[k] - __bfloat162float(hi[k]));
    }
    ((uint2*)gBhi)[s] = make_uint2(pack_bf2(hi[0], hi[1]), pack_bf2(hi[2], hi[3]));
    ((uint2*)gBlo)[s] = make_uint2(pack_bf2(lo[0], lo[1]), pack_bf2(lo[2], lo[3]));
}

// ---------------------------------------------------------------------------
// Kernel 1: energy = h @ h^T via 4-product bf16 mma.m16n8k16, symmetric tiles
// ---------------------------------------------------------------------------
__global__ __launch_bounds__(256, 2)
void energy_tc_kernel(float* __restrict__ out) {
    extern __shared__ float smem[];
    const uint32_t sb = smem_u32(smem);
    const int tid  = threadIdx.x;
    const int wid  = tid >> 5;
    const int lane = tid & 31;
    const int wm = wid & 1;          // 2 row blocks of 64
    const int wn = wid >> 1;         // 4 col blocks of 32
    const int gq = lane >> 2;
    const int tg = lane & 3;

    const int b = blockIdx.y;
    const int idx = blockIdx.x;
    const int rev = NTRI - 1 - idx;
    const int rrow = (int)((sqrtf(8.0f * (float)rev + 1.0f) - 1.0f) * 0.5f);
    const int ti = NTILES - 1 - rrow;
    const int tj = NTILES - 1 - (rev - (rrow * (rrow + 1)) / 2);
    const bool diag = (ti == tj);

    // chunk-region element bases (4096 bf16 = 8KB per chunk region)
    const size_t aoff = ((size_t)(b * NTILES + ti) * NCHUNK) * 4096;
    const size_t boff = ((size_t)(b * NTILES + tj) * NCHUNK) * 4096;
    const __nv_bfloat16* srcs[4] = { gAhi + aoff, gAlo + aoff, gBhi + boff, gBlo + boff };

    float acc[16][4];
#pragma unroll
    for (int f = 0; f < 16; f++)
#pragma unroll
        for (int c = 0; c < 4; c++) acc[f][c] = 0.0f;

    auto prefetch = [&](int chunk, int stage) {
#pragma unroll
        for (int r = 0; r < 4; r++) {
#pragma unroll
            for (int q = 0; q < 2; q++) {
                const int seg = tid + q * 256;   // 0..511 (16B segments)
                CP_ASYNC16(sb + (uint32_t)(stage * STAGE_B + r * 8192 + seg * 16),
                           srcs[r] + (size_t)chunk * 4096 + seg * 8);
            }
        }
        CP_COMMIT();
    };

    prefetch(0, 0);

    for (int c = 0; c < NCHUNK; c++) {
        if (c + 1 < NCHUNK) { prefetch(c + 1, (c + 1) & 1); CP_WAIT(1); }
        else                { CP_WAIT(0); }
        __syncthreads();

        const uint32_t st = sb + (uint32_t)((c & 1) * STAGE_B);
        const uint32_t sAhi = st, sAlo = st + 8192, sBhi = st + 16384, sBlo = st + 24576;

#pragma unroll
        for (int kf = 0; kf < 2; kf++) {
            uint32_t bh[4][2], bl[4][2];
#pragma unroll
            for (int nf = 0; nf < 4; nf++) {
                const uint32_t bo = (uint32_t)(((kf * 16 + wn * 4 + nf) * 32 + lane) * 8);
                LDS_V2(bh[nf], sBhi + bo);
                LDS_V2(bl[nf], sBlo + bo);
            }
#pragma unroll
            for (int mf = 0; mf < 4; mf++) {
                uint32_t ah[4], al[4];
                const uint32_t ao = (uint32_t)(((kf * 8 + wm * 4 + mf) * 32 + lane) * 16);
                LDS_V4(ah, sAhi + ao);
                LDS_V4(al, sAlo + ao);
#pragma unroll
                for (int nf = 0; nf < 4; nf++) {
                    float* cc = acc[mf * 4 + nf];
                    MMA_BF16(cc, ah, bh[nf]);   // hi*hi
                    MMA_BF16(cc, ah, bl[nf]);   // hi*lo
                    MMA_BF16(cc, al, bh[nf]);   // lo*hi
                    MMA_BF16(cc, al, bl[nf]);   // lo*lo
                }
            }
        }
        __syncthreads();
    }

    // ---- epilogue: acc -> padded smem (128x129) -> coalesced global (tile + mirror)
    float* sf = smem;
#pragma unroll
    for (int mf = 0; mf < 4; mf++)
#pragma unroll
        for (int nf = 0; nf < 4; nf++) {
            const int r0 = wm * 64 + mf * 16 + gq;
            const int c0 = wn * 32 + nf * 8 + tg * 2;
            const float* cc = acc[mf * 4 + nf];
            sf[r0 * 129 + c0]           = cc[0];
            sf[r0 * 129 + c0 + 1]       = cc[1];
            sf[(r0 + 8) * 129 + c0]     = cc[2];
            sf[(r0 + 8) * 129 + c0 + 1] = cc[3];
        }
    __syncthreads();

    float* __restrict__ ob = out + (size_t)b * NN * NN;
    const int rbase = ti * TILE;
    const int cbase = tj * TILE;

    for (int i2 = tid; i2 < 128 * 32; i2 += 256) {
        const int row = i2 >> 5;
        const int c4 = (i2 & 31) * 4;
        float4 v = make_float4(sf[row * 129 + c4], sf[row * 129 + c4 + 1],
                               sf[row * 129 + c4 + 2], sf[row * 129 + c4 + 3]);
        *(float4*)(ob + (size_t)(rbase + row) * NN + cbase + c4) = v;
    }
    if (!diag) {
        for (int i2 = tid; i2 < 128 * 32; i2 += 256) {
            const int mrow = i2 >> 5;
            const int c4 = (i2 & 31) * 4;
            float4 v = make_float4(sf[(c4 + 0) * 129 + mrow], sf[(c4 + 1) * 129 + mrow],
                                   sf[(c4 + 2) * 129 + mrow], sf[(c4 + 3) * 129 + mrow]);
            *(float4*)(ob + (size_t)(cbase + mrow) * NN + rbase + c4) = v;
        }
    }
}

// ---------------------------------------------------------------------------
// Kernel 2: per-row  t = (rowmax(e) - e) * adj;  out = softmax(t)  (unchanged)
// ---------------------------------------------------------------------------
__device__ __forceinline__ float warp_max(float v) {
#pragma unroll
    for (int o = 16; o > 0; o >>= 1) v = fmaxf(v, __shfl_xor_sync(0xFFFFFFFFu, v, o));
    return v;
}
__device__ __forceinline__ float warp_sum(float v) {
#pragma unroll
    for (int o = 16; o > 0; o >>= 1) v += __shfl_xor_sync(0xFFFFFFFFu, v, o);
    return v;
}

__global__ __launch_bounds__(256, 8)
void softmax_adj_kernel(float* __restrict__ out, const float* __restrict__ adj) {
    const size_t row = blockIdx.x;
    float* __restrict__ e = out + row * NN;
    const float* __restrict__ a = adj + row * NN;

    __shared__ float red[8];
    const int tid = threadIdx.x, lane = tid & 31, wid = tid >> 5;

    float4 e0 = ((const float4*)e)[tid];
    float4 e1 = ((const float4*)e)[tid + 256];

    float m = fmaxf(fmaxf(fmaxf(e0.x, e0.y), fmaxf(e0.z, e0.w)),
                    fmaxf(fmaxf(e1.x, e1.y), fmaxf(e1.z, e1.w)));
    m = warp_max(m);
    if (lane == 0) red[wid] = m;
    __syncthreads();
    if (wid == 0) {
        float v = red[lane & 7];
        v = fmaxf(v, __shfl_xor_sync(0xFFFFFFFFu, v, 4));
        v = fmaxf(v, __shfl_xor_sync(0xFFFFFFFFu, v, 2));
        v = fmaxf(v, __shfl_xor_sync(0xFFFFFFFFu, v, 1));
        if (lane == 0) red[0] = v;
    }
    __syncthreads();
    const float M = red[0];
    __syncthreads();

    float4 a0 = ((const float4*)a)[tid];
    float4 a1 = ((const float4*)a)[tid + 256];

    float t[8];
    t[0] = (M - e0.x) * a0.x;  t[1] = (M - e0.y) * a0.y;
    t[2] = (M - e0.z) * a0.z;  t[3] = (M - e0.w) * a0.w;
    t[4] = (M - e1.x) * a1.x;  t[5] = (M - e1.y) * a1.y;
    t[6] = (M - e1.z) * a1.z;  t[7] = (M - e1.w) * a1.w;

    float tm = t[0];
#pragma unroll
    for (int k = 1; k < 8; k++) tm = fmaxf(tm, t[k]);
    tm = warp_max(tm);
    if (lane == 0) red[wid] = tm;
    __syncthreads();
    if (wid == 0) {
        float v = red[lane & 7];
        v = fmaxf(v, __shfl_xor_sync(0xFFFFFFFFu, v, 4));
        v = fmaxf(v, __shfl_xor_sync(0xFFFFFFFFu, v, 2));
        v = fmaxf(v, __shfl_xor_sync(0xFFFFFFFFu, v, 1));
        if (lane == 0) red[0] = v;
    }
    __syncthreads();
    const float T = red[0];
    __syncthreads();

    float p[8], s = 0.0f;
#pragma unroll
    for (int k = 0; k < 8; k++) { p[k] = __expf(t[k] - T); s += p[k]; }
    s = warp_sum(s);
    if (lane == 0) red[wid] = s;
    __syncthreads();
    if (wid == 0) {
        float v = red[lane & 7];
        v += __shfl_xor_sync(0xFFFFFFFFu, v, 4);
        v += __shfl_xor_sync(0xFFFFFFFFu, v, 2);
        v += __shfl_xor_sync(0xFFFFFFFFu, v, 1);
        if (lane == 0) red[0] = v;
    }
    __syncthreads();
    const float inv = 1.0f / red[0];

    ((float4*)e)[tid]       = make_float4(p[0] * inv, p[1] * inv, p[2] * inv, p[3] * inv);
    ((float4*)e)[tid + 256] = make_float4(p[4] * inv, p[5] * inv, p[6] * inv, p[7] * inv);
}

// ---------------------------------------------------------------------------
extern "C" void kernel_launch(void* const* d_in, const int* in_sizes, int n_in,
                              void* d_out, int out_size) {
    const float* h   = (const float*)d_in[0];   // [B, N, D]
    const float* adj = (const float*)d_in[1];   // [B, N, N]
    float* out = (float*)d_out;                 // [B, N, N]

    cudaFuncSetAttribute(energy_tc_kernel, cudaFuncAttributeMaxDynamicSharedMemorySize, SMEM_DYN);

    pack_a_kernel<<<2048, 256>>>(h);
    pack_b_kernel<<<4096, 256>>>(h);

    dim3 ggrid(NTRI, BATCH);
    energy_tc_kernel<<<ggrid, 256, SMEM_DYN>>>(out);

    softmax_adj_kernel<<<BATCH * NN, 256>>>(out, adj);
}

// round 6
// speedup vs baseline: 2.3130x; 1.0822x over previous
#include <cuda_runtime.h>
#include <cuda_bf16.h>
#include <cstdint>
#include <math.h>

// Problem constants: B=8, N=2048, D=256
#define BATCH 8
#define NN 2048
#define DD 256

#define TILE 128
#define NTILES 16              // NN / TILE
#define NTRI 136               // NTILES*(NTILES+1)/2
#define NCHUNK 8               // K chunks of 32

// smem: per stage 4 regions x 8KB (Ahi, Alo, Bhi, Blo) = 32KB; 2 stages = 64KB
#define STAGE_B 32768
#define SMEM_DYN 66560         // >= 128*129*4 (epilogue) and >= 2*STAGE_B

// ---------------------------------------------------------------------------
// bf16 split operands in FRAGMENT-MAJOR layout (device globals)
// A-layout: [b][rb][chunk][kf][mf][thread 16B]   (m16n8k16 A fragments)
// B-layout: [b][rb][chunk][kf][nf][thread 8B]    (m16n8k16 B fragments)
// ---------------------------------------------------------------------------
__device__ __nv_bfloat16 gAhi[BATCH * NN * DD];
__device__ __nv_bfloat16 gAlo[BATCH * NN * DD];
__device__ __nv_bfloat16 gBhi[BATCH * NN * DD];
__device__ __nv_bfloat16 gBlo[BATCH * NN * DD];

// ---------------------------------------------------------------------------
// helpers
// ---------------------------------------------------------------------------
__device__ __forceinline__ uint32_t smem_u32(const void* p) {
    uint32_t a;
    asm("{ .reg .u64 t; cvta.to.shared.u64 t, %1; cvt.u32.u64 %0, t; }" : "=r"(a) : "l"(p));
    return a;
}
#define CP_ASYNC16(dst, src) \
    asm volatile("cp.async.cg.shared.global [%0], [%1], 16;" :: "r"(dst), "l"(src))
#define CP_COMMIT() asm volatile("cp.async.commit_group;")
#define CP_WAIT(n)  asm volatile("cp.async.wait_group %0;" :: "n"(n))

#define LDS_V4(r, addr) \
    asm volatile("ld.shared.v4.b32 {%0,%1,%2,%3}, [%4];" \
        : "=r"((r)[0]), "=r"((r)[1]), "=r"((r)[2]), "=r"((r)[3]) : "r"(addr))
#define LDS_V2(r, addr) \
    asm volatile("ld.shared.v2.b32 {%0,%1}, [%2];" \
        : "=r"((r)[0]), "=r"((r)[1]) : "r"(addr))

#define MMA_BF16(c, a, b) \
    asm volatile("mma.sync.aligned.m16n8k16.row.col.f32.bf16.bf16.f32 " \
        "{%0,%1,%2,%3}, {%4,%5,%6,%7}, {%8,%9}, {%0,%1,%2,%3};" \
        : "+f"((c)[0]), "+f"((c)[1]), "+f"((c)[2]), "+f"((c)[3]) \
        : "r"((a)[0]), "r"((a)[1]), "r"((a)[2]), "r"((a)[3]), \
          "r"((b)[0]), "r"((b)[1]))

__device__ __forceinline__ uint32_t pack_bf2(__nv_bfloat16 a, __nv_bfloat16 b) {
    return (uint32_t)__bfloat16_as_ushort(a) | ((uint32_t)__bfloat16_as_ushort(b) << 16);
}

// ---------------------------------------------------------------------------
// pack_a: h (fp32) -> gAhi/gAlo in m16n8k16 A-fragment-major layout
// ---------------------------------------------------------------------------
__global__ __launch_bounds__(256)
void pack_a_kernel(const float* __restrict__ h) {
    const uint32_t s = blockIdx.x * 256 + threadIdx.x;      // 0..524287
    const int t = s & 31, mf = (s >> 5) & 7, kf = (s >> 8) & 1;
    const int chunk = (s >> 9) & 7, rb = (s >> 12) & 15, b = s >> 16;
    const int row = rb * 128 + mf * 16 + (t >> 2);
    const int kb  = chunk * 32 + kf * 16 + (t & 3) * 2;
    const float* base = h + ((size_t)(b * NN + row)) * DD + kb;
    float2 L00 = *(const float2*)(base);
    float2 L10 = *(const float2*)(base + 8 * DD);
    float2 L01 = *(const float2*)(base + 8);
    float2 L11 = *(const float2*)(base + 8 * DD + 8);

    float x[8] = { L00.x, L00.y, L10.x, L10.y, L01.x, L01.y, L11.x, L11.y };
    __nv_bfloat16 hi[8], lo[8];
#pragma unroll
    for (int k = 0; k < 8; k++) {
        hi[k] = __float2bfloat16(x[k]);
        lo[k] = __float2bfloat16(x[k] - __bfloat162float(hi[k]));
    }
    uint4 vh = make_uint4(pack_bf2(hi[0], hi[1]), pack_bf2(hi[2], hi[3]),
                          pack_bf2(hi[4], hi[5]), pack_bf2(hi[6], hi[7]));
    uint4 vl = make_uint4(pack_bf2(lo[0], lo[1]), pack_bf2(lo[2], lo[3]),
                          pack_bf2(lo[4], lo[5]), pack_bf2(lo[6], lo[7]));
    ((uint4*)gAhi)[s] = vh;
    ((uint4*)gAlo)[s] = vl;
}

// ---------------------------------------------------------------------------
// pack_b: h (fp32) -> gBhi/gBlo in m16n8k16 B-fragment-major layout
// ---------------------------------------------------------------------------
__global__ __launch_bounds__(256)
void pack_b_kernel(const float* __restrict__ h) {
    const uint32_t s = blockIdx.x * 256 + threadIdx.x;      // 0..1048575
    const int t = s & 31, nf = (s >> 5) & 15, kf = (s >> 9) & 1;
    const int chunk = (s >> 10) & 7, rb = (s >> 13) & 15, b = s >> 17;
    const int n  = rb * 128 + nf * 8 + (t >> 2);
    const int kb = chunk * 32 + kf * 16 + (t & 3) * 2;
    const float* base = h + ((size_t)(b * NN + n)) * DD + kb;
    float2 K0 = *(const float2*)(base);
    float2 K1 = *(const float2*)(base + 8);

    float x[4] = { K0.x, K0.y, K1.x, K1.y };
    __nv_bfloat16 hi[4], lo[4];
#pragma unroll
    for (int k = 0; k < 4; k++) {
        hi[k] = __float2bfloat16(x[k]);
        lo[k] = __float2bfloat16(x[k] - __bfloat162float(hi[k]));
    }
    ((uint2*)gBhi)[s] = make_uint2(pack_bf2(hi[0], hi[1]), pack_bf2(hi[2], hi[3]));
    ((uint2*)gBlo)[s] = make_uint2(pack_bf2(lo[0], lo[1]), pack_bf2(lo[2], lo[3]));
}

// ---------------------------------------------------------------------------
// Kernel 1: energy = h @ h^T via 3-product bf16 mma.m16n8k16, symmetric tiles
// (hi*hi + hi*lo + lo*hi; dropped lo*lo contributes ~1.6e-5 abs in logits)
// ---------------------------------------------------------------------------
__global__ __launch_bounds__(256, 2)
void energy_tc_kernel(float* __restrict__ out) {
    extern __shared__ float smem[];
    const uint32_t sb = smem_u32(smem);
    const int tid  = threadIdx.x;
    const int wid  = tid >> 5;
    const int lane = tid & 31;
    const int wm = wid & 1;          // 2 row blocks of 64
    const int wn = wid >> 1;         // 4 col blocks of 32
    const int gq = lane >> 2;
    const int tg = lane & 3;

    const int b = blockIdx.y;
    const int idx = blockIdx.x;
    const int rev = NTRI - 1 - idx;
    const int rrow = (int)((sqrtf(8.0f * (float)rev + 1.0f) - 1.0f) * 0.5f);
    const int ti = NTILES - 1 - rrow;
    const int tj = NTILES - 1 - (rev - (rrow * (rrow + 1)) / 2);
    const bool diag = (ti == tj);

    const size_t aoff = ((size_t)(b * NTILES + ti) * NCHUNK) * 4096;
    const size_t boff = ((size_t)(b * NTILES + tj) * NCHUNK) * 4096;
    const __nv_bfloat16* srcs[4] = { gAhi + aoff, gAlo + aoff, gBhi + boff, gBlo + boff };

    float acc[16][4];
#pragma unroll
    for (int f = 0; f < 16; f++)
#pragma unroll
        for (int c = 0; c < 4; c++) acc[f][c] = 0.0f;

    auto prefetch = [&](int chunk, int stage) {
#pragma unroll
        for (int r = 0; r < 4; r++) {
#pragma unroll
            for (int q = 0; q < 2; q++) {
                const int seg = tid + q * 256;   // 0..511 (16B segments)
                CP_ASYNC16(sb + (uint32_t)(stage * STAGE_B + r * 8192 + seg * 16),
                           srcs[r] + (size_t)chunk * 4096 + seg * 8);
            }
        }
        CP_COMMIT();
    };

    prefetch(0, 0);

    for (int c = 0; c < NCHUNK; c++) {
        if (c + 1 < NCHUNK) { prefetch(c + 1, (c + 1) & 1); CP_WAIT(1); }
        else                { CP_WAIT(0); }
        __syncthreads();

        const uint32_t st = sb + (uint32_t)((c & 1) * STAGE_B);
        const uint32_t sAhi = st, sAlo = st + 8192, sBhi = st + 16384, sBlo = st + 24576;

#pragma unroll
        for (int kf = 0; kf < 2; kf++) {
            uint32_t bh[4][2], bl[4][2];
#pragma unroll
            for (int nf = 0; nf < 4; nf++) {
                const uint32_t bo = (uint32_t)(((kf * 16 + wn * 4 + nf) * 32 + lane) * 8);
                LDS_V2(bh[nf], sBhi + bo);
                LDS_V2(bl[nf], sBlo + bo);
            }
#pragma unroll
            for (int mf = 0; mf < 4; mf++) {
                uint32_t ah[4], al[4];
                const uint32_t ao = (uint32_t)(((kf * 8 + wm * 4 + mf) * 32 + lane) * 16);
                LDS_V4(ah, sAhi + ao);
                LDS_V4(al, sAlo + ao);
#pragma unroll
                for (int nf = 0; nf < 4; nf++) {
                    float* cc = acc[mf * 4 + nf];
                    MMA_BF16(cc, ah, bh[nf]);   // hi*hi
                    MMA_BF16(cc, ah, bl[nf]);   // hi*lo
                    MMA_BF16(cc, al, bh[nf]);   // lo*hi
                }
            }
        }
        __syncthreads();
    }

    // ---- epilogue: acc -> padded smem (128x129) -> coalesced global (tile + mirror)
    float* sf = smem;
#pragma unroll
    for (int mf = 0; mf < 4; mf++)
#pragma unroll
        for (int nf = 0; nf < 4; nf++) {
            const int r0 = wm * 64 + mf * 16 + gq;
            const int c0 = wn * 32 + nf * 8 + tg * 2;
            const float* cc = acc[mf * 4 + nf];
            sf[r0 * 129 + c0]           = cc[0];
            sf[r0 * 129 + c0 + 1]       = cc[1];
            sf[(r0 + 8) * 129 + c0]     = cc[2];
            sf[(r0 + 8) * 129 + c0 + 1] = cc[3];
        }
    __syncthreads();

    float* __restrict__ ob = out + (size_t)b * NN * NN;
    const int rbase = ti * TILE;
    const int cbase = tj * TILE;

    for (int i2 = tid; i2 < 128 * 32; i2 += 256) {
        const int row = i2 >> 5;
        const int c4 = (i2 & 31) * 4;
        float4 v = make_float4(sf[row * 129 + c4], sf[row * 129 + c4 + 1],
                               sf[row * 129 + c4 + 2], sf[row * 129 + c4 + 3]);
        *(float4*)(ob + (size_t)(rbase + row) * NN + cbase + c4) = v;
    }
    if (!diag) {
        for (int i2 = tid; i2 < 128 * 32; i2 += 256) {
            const int mrow = i2 >> 5;
            const int c4 = (i2 & 31) * 4;
            float4 v = make_float4(sf[(c4 + 0) * 129 + mrow], sf[(c4 + 1) * 129 + mrow],
                                   sf[(c4 + 2) * 129 + mrow], sf[(c4 + 3) * 129 + mrow]);
            *(float4*)(ob + (size_t)(cbase + mrow) * NN + rbase + c4) = v;
        }
    }
}

// ---------------------------------------------------------------------------
// Kernel 2: per-row  t = (rowmax(e) - e) * adj;  out = softmax(t)  (unchanged)
// ---------------------------------------------------------------------------
__device__ __forceinline__ float warp_max(float v) {
#pragma unroll
    for (int o = 16; o > 0; o >>= 1) v = fmaxf(v, __shfl_xor_sync(0xFFFFFFFFu, v, o));
    return v;
}
__device__ __forceinline__ float warp_sum(float v) {
#pragma unroll
    for (int o = 16; o > 0; o >>= 1) v += __shfl_xor_sync(0xFFFFFFFFu, v, o);
    return v;
}

__global__ __launch_bounds__(256, 8)
void softmax_adj_kernel(float* __restrict__ out, const float* __restrict__ adj) {
    const size_t row = blockIdx.x;
    float* __restrict__ e = out + row * NN;
    const float* __restrict__ a = adj + row * NN;

    __shared__ float red[8];
    const int tid = threadIdx.x, lane = tid & 31, wid = tid >> 5;

    float4 e0 = ((const float4*)e)[tid];
    float4 e1 = ((const float4*)e)[tid + 256];

    float m = fmaxf(fmaxf(fmaxf(e0.x, e0.y), fmaxf(e0.z, e0.w)),
                    fmaxf(fmaxf(e1.x, e1.y), fmaxf(e1.z, e1.w)));
    m = warp_max(m);
    if (lane == 0) red[wid] = m;
    __syncthreads();
    if (wid == 0) {
        float v = red[lane & 7];
        v = fmaxf(v, __shfl_xor_sync(0xFFFFFFFFu, v, 4));
        v = fmaxf(v, __shfl_xor_sync(0xFFFFFFFFu, v, 2));
        v = fmaxf(v, __shfl_xor_sync(0xFFFFFFFFu, v, 1));
        if (lane == 0) red[0] = v;
    }
    __syncthreads();
    const float M = red[0];
    __syncthreads();

    float4 a0 = ((const float4*)a)[tid];
    float4 a1 = ((const float4*)a)[tid + 256];

    float t[8];
    t[0] = (M - e0.x) * a0.x;  t[1] = (M - e0.y) * a0.y;
    t[2] = (M - e0.z) * a0.z;  t[3] = (M - e0.w) * a0.w;
    t[4] = (M - e1.x) * a1.x;  t[5] = (M - e1.y) * a1.y;
    t[6] = (M - e1.z) * a1.z;  t[7] = (M - e1.w) * a1.w;

    float tm = t[0];
#pragma unroll
    for (int k = 1; k < 8; k++) tm = fmaxf(tm, t[k]);
    tm = warp_max(tm);
    if (lane == 0) red[wid] = tm;
    __syncthreads();
    if (wid == 0) {
        float v = red[lane & 7];
        v = fmaxf(v, __shfl_xor_sync(0xFFFFFFFFu, v, 4));
        v = fmaxf(v, __shfl_xor_sync(0xFFFFFFFFu, v, 2));
        v = fmaxf(v, __shfl_xor_sync(0xFFFFFFFFu, v, 1));
        if (lane == 0) red[0] = v;
    }
    __syncthreads();
    const float T = red[0];
    __syncthreads();

    float p[8], s = 0.0f;
#pragma unroll
    for (int k = 0; k < 8; k++) { p[k] = __expf(t[k] - T); s += p[k]; }
    s = warp_sum(s);
    if (lane == 0) red[wid] = s;
    __syncthreads();
    if (wid == 0) {
        float v = red[lane & 7];
        v += __shfl_xor_sync(0xFFFFFFFFu, v, 4);
        v += __shfl_xor_sync(0xFFFFFFFFu, v, 2);
        v += __shfl_xor_sync(0xFFFFFFFFu, v, 1);
        if (lane == 0) red[0] = v;
    }
    __syncthreads();
    const float inv = 1.0f / red[0];

    ((float4*)e)[tid]       = make_float4(p[0] * inv, p[1] * inv, p[2] * inv, p[3] * inv);
    ((float4*)e)[tid + 256] = make_float4(p[4] * inv, p[5] * inv, p[6] * inv, p[7] * inv);
}

// ---------------------------------------------------------------------------
extern "C" void kernel_launch(void* const* d_in, const int* in_sizes, int n_in,
                              void* d_out, int out_size) {
    const float* h   = (const float*)d_in[0];   // [B, N, D]
    const float* adj = (const float*)d_in[1];   // [B, N, N]
    float* out = (float*)d_out;                 // [B, N, N]

    cudaFuncSetAttribute(energy_tc_kernel, cudaFuncAttributeMaxDynamicSharedMemorySize, SMEM_DYN);

    pack_a_kernel<<<2048, 256>>>(h);
    pack_b_kernel<<<4096, 256>>>(h);

    dim3 ggrid(NTRI, BATCH);
    energy_tc_kernel<<<ggrid, 256, SMEM_DYN>>>(out);

    softmax_adj_kernel<<<BATCH * NN, 256>>>(out, adj);
}

// round 7
// speedup vs baseline: 2.3215x; 1.0037x over previous
#include <cuda_runtime.h>
#include <cuda_bf16.h>
#include <cstdint>
#include <math.h>

// Problem constants: B=8, N=2048, D=256
#define BATCH 8
#define NN 2048
#define DD 256

#define TILE 128
#define NTILES 16              // NN / TILE
#define NTRI 136               // NTILES*(NTILES+1)/2
#define NCHUNK 8               // K chunks of 32
#define PHASE_B 2              // batches per phase (L2-resident energy slice)

// smem: per stage 4 regions x 8KB (Ahi, Alo, Bhi, Blo) = 32KB; 2 stages = 64KB
#define STAGE_B 32768
#define SMEM_DYN 66560         // >= 128*129*4 (epilogue) and >= 2*STAGE_B

// ---------------------------------------------------------------------------
// bf16 split operands in FRAGMENT-MAJOR layout (device globals)
// A-layout: [b][rb][chunk][kf][mf(8)][thread 16B]   (m16n8k16 A fragments)
// B-layout: [b][rb][chunk][kf][nf(16)][thread 8B]   (m16n8k16 B fragments)
// ---------------------------------------------------------------------------
__device__ __nv_bfloat16 gAhi[BATCH * NN * DD];
__device__ __nv_bfloat16 gAlo[BATCH * NN * DD];
__device__ __nv_bfloat16 gBhi[BATCH * NN * DD];
__device__ __nv_bfloat16 gBlo[BATCH * NN * DD];

// ---------------------------------------------------------------------------
// helpers
// ---------------------------------------------------------------------------
__device__ __forceinline__ uint32_t smem_u32(const void* p) {
    uint32_t a;
    asm("{ .reg .u64 t; cvta.to.shared.u64 t, %1; cvt.u32.u64 %0, t; }" : "=r"(a) : "l"(p));
    return a;
}
#define CP_ASYNC16(dst, src) \
    asm volatile("cp.async.cg.shared.global [%0], [%1], 16;" :: "r"(dst), "l"(src))
#define CP_COMMIT() asm volatile("cp.async.commit_group;")
#define CP_WAIT(n)  asm volatile("cp.async.wait_group %0;" :: "n"(n))

#define LDS_V4(r, addr) \
    asm volatile("ld.shared.v4.b32 {%0,%1,%2,%3}, [%4];" \
        : "=r"((r)[0]), "=r"((r)[1]), "=r"((r)[2]), "=r"((r)[3]) : "r"(addr))
#define LDS_V2(r, addr) \
    asm volatile("ld.shared.v2.b32 {%0,%1}, [%2];" \
        : "=r"((r)[0]), "=r"((r)[1]) : "r"(addr))

#define MMA_BF16(c, a, b) \
    asm volatile("mma.sync.aligned.m16n8k16.row.col.f32.bf16.bf16.f32 " \
        "{%0,%1,%2,%3}, {%4,%5,%6,%7}, {%8,%9}, {%0,%1,%2,%3};" \
        : "+f"((c)[0]), "+f"((c)[1]), "+f"((c)[2]), "+f"((c)[3]) \
        : "r"((a)[0]), "r"((a)[1]), "r"((a)[2]), "r"((a)[3]), \
          "r"((b)[0]), "r"((b)[1]))

__device__ __forceinline__ uint32_t pack_bf2(__nv_bfloat16 a, __nv_bfloat16 b) {
    return (uint32_t)__bfloat16_as_ushort(a) | ((uint32_t)__bfloat16_as_ushort(b) << 16);
}

// ---------------------------------------------------------------------------
// pack_a: h (fp32) -> gAhi/gAlo in m16n8k16 A-fragment-major layout
// ---------------------------------------------------------------------------
__global__ __launch_bounds__(256)
void pack_a_kernel(const float* __restrict__ h) {
    const uint32_t s = blockIdx.x * 256 + threadIdx.x;      // 0..524287
    const int t = s & 31, mf = (s >> 5) & 7, kf = (s >> 8) & 1;
    const int chunk = (s >> 9) & 7, rb = (s >> 12) & 15, b = s >> 16;
    const int row = rb * 128 + mf * 16 + (t >> 2);
    const int kb  = chunk * 32 + kf * 16 + (t & 3) * 2;
    const float* base = h + ((size_t)(b * NN + row)) * DD + kb;
    float2 L00 = *(const float2*)(base);
    float2 L10 = *(const float2*)(base + 8 * DD);
    float2 L01 = *(const float2*)(base + 8);
    float2 L11 = *(const float2*)(base + 8 * DD + 8);

    float x[8] = { L00.x, L00.y, L10.x, L10.y, L01.x, L01.y, L11.x, L11.y };
    __nv_bfloat16 hi[8], lo[8];
#pragma unroll
    for (int k = 0; k < 8; k++) {
        hi[k] = __float2bfloat16(x[k]);
        lo[k] = __float2bfloat16(x[k] - __bfloat162float(hi[k]));
    }
    uint4 vh = make_uint4(pack_bf2(hi[0], hi[1]), pack_bf2(hi[2], hi[3]),
                          pack_bf2(hi[4], hi[5]), pack_bf2(hi[6], hi[7]));
    uint4 vl = make_uint4(pack_bf2(lo[0], lo[1]), pack_bf2(lo[2], lo[3]),
                          pack_bf2(lo[4], lo[5]), pack_bf2(lo[6], lo[7]));
    ((uint4*)gAhi)[s] = vh;
    ((uint4*)gAlo)[s] = vl;
}

// ---------------------------------------------------------------------------
// pack_b: h (fp32) -> gBhi/gBlo in m16n8k16 B-fragment-major layout
// ---------------------------------------------------------------------------
__global__ __launch_bounds__(256)
void pack_b_kernel(const float* __restrict__ h) {
    const uint32_t s = blockIdx.x * 256 + threadIdx.x;      // 0..1048575
    const int t = s & 31, nf = (s >> 5) & 15, kf = (s >> 9) & 1;
    const int chunk = (s >> 10) & 7, rb = (s >> 13) & 15, b = s >> 17;
    const int n  = rb * 128 + nf * 8 + (t >> 2);
    const int kb = chunk * 32 + kf * 16 + (t & 3) * 2;
    const float* base = h + ((size_t)(b * NN + n)) * DD + kb;
    float2 K0 = *(const float2*)(base);
    float2 K1 = *(const float2*)(base + 8);

    float x[4] = { K0.x, K0.y, K1.x, K1.y };
    __nv_bfloat16 hi[4], lo[4];
#pragma unroll
    for (int k = 0; k < 4; k++) {
        hi[k] = __float2bfloat16(x[k]);
        lo[k] = __float2bfloat16(x[k] - __bfloat162float(hi[k]));
    }
    ((uint2*)gBhi)[s] = make_uint2(pack_bf2(hi[0], hi[1]), pack_bf2(hi[2], hi[3]));
    ((uint2*)gBlo)[s] = make_uint2(pack_bf2(lo[0], lo[1]), pack_bf2(lo[2], lo[3]));
}

// ---------------------------------------------------------------------------
// Kernel 1: energy = h @ h^T, 3-product bf16 mma.m16n8k16, symmetric tiles.
// 128 threads, 4 warps, 64x64 warp tiles (A/B LDS redundancy x2 each).
// ---------------------------------------------------------------------------
__global__ __launch_bounds__(128, 2)
void energy_tc_kernel(float* __restrict__ out, int b0) {
    extern __shared__ float smem[];
    const uint32_t sb = smem_u32(smem);
    const int tid  = threadIdx.x;
    const int wid  = tid >> 5;
    const int lane = tid & 31;
    const int wm = wid & 1;          // 2 row halves of 64
    const int wn = wid >> 1;         // 2 col halves of 64
    const int gq = lane >> 2;
    const int tg = lane & 3;

    const int b = b0 + blockIdx.y;
    const int idx = blockIdx.x;
    const int rev = NTRI - 1 - idx;
    const int rrow = (int)((sqrtf(8.0f * (float)rev + 1.0f) - 1.0f) * 0.5f);
    const int ti = NTILES - 1 - rrow;
    const int tj = NTILES - 1 - (rev - (rrow * (rrow + 1)) / 2);
    const bool diag = (ti == tj);

    const size_t aoff = ((size_t)(b * NTILES + ti) * NCHUNK) * 4096;
    const size_t boff = ((size_t)(b * NTILES + tj) * NCHUNK) * 4096;
    const __nv_bfloat16* srcs[4] = { gAhi + aoff, gAlo + aoff, gBhi + boff, gBlo + boff };

    float acc[32][4];                // [mf*8+nf][4]
#pragma unroll
    for (int f = 0; f < 32; f++)
#pragma unroll
        for (int c = 0; c < 4; c++) acc[f][c] = 0.0f;

    auto prefetch = [&](int chunk, int stage) {
#pragma unroll
        for (int r = 0; r < 4; r++) {
#pragma unroll
            for (int q = 0; q < 4; q++) {
                const int seg = tid + q * 128;   // 0..511 (16B segments)
                CP_ASYNC16(sb + (uint32_t)(stage * STAGE_B + r * 8192 + seg * 16),
                           srcs[r] + (size_t)chunk * 4096 + seg * 8);
            }
        }
        CP_COMMIT();
    };

    prefetch(0, 0);

    for (int c = 0; c < NCHUNK; c++) {
        if (c + 1 < NCHUNK) { prefetch(c + 1, (c + 1) & 1); CP_WAIT(1); }
        else                { CP_WAIT(0); }
        __syncthreads();

        const uint32_t st = sb + (uint32_t)((c & 1) * STAGE_B);
        const uint32_t sAhi = st, sAlo = st + 8192, sBhi = st + 16384, sBlo = st + 24576;

#pragma unroll
        for (int kf = 0; kf < 2; kf++) {
            uint32_t bh[8][2], bl[8][2];
#pragma unroll
            for (int nf = 0; nf < 8; nf++) {
                const uint32_t bo = (uint32_t)(((kf * 16 + wn * 8 + nf) * 32 + lane) * 8);
                LDS_V2(bh[nf], sBhi + bo);
                LDS_V2(bl[nf], sBlo + bo);
            }
#pragma unroll
            for (int mf = 0; mf < 4; mf++) {
                uint32_t ah[4], al[4];
                const uint32_t ao = (uint32_t)(((kf * 8 + wm * 4 + mf) * 32 + lane) * 16);
                LDS_V4(ah, sAhi + ao);
                LDS_V4(al, sAlo + ao);
#pragma unroll
                for (int nf = 0; nf < 8; nf++) {
                    float* cc = acc[mf * 8 + nf];
                    MMA_BF16(cc, ah, bh[nf]);   // hi*hi
                    MMA_BF16(cc, ah, bl[nf]);   // hi*lo
                    MMA_BF16(cc, al, bh[nf]);   // lo*hi
                }
            }
        }
        __syncthreads();
    }

    // ---- epilogue: acc -> padded smem (128x129) -> coalesced global (tile + mirror)
    float* sf = smem;
#pragma unroll
    for (int mf = 0; mf < 4; mf++)
#pragma unroll
        for (int nf = 0; nf < 8; nf++) {
            const int r0 = wm * 64 + mf * 16 + gq;
            const int c0 = wn * 64 + nf * 8 + tg * 2;
            const float* cc = acc[mf * 8 + nf];
            sf[r0 * 129 + c0]           = cc[0];
            sf[r0 * 129 + c0 + 1]       = cc[1];
            sf[(r0 + 8) * 129 + c0]     = cc[2];
            sf[(r0 + 8) * 129 + c0 + 1] = cc[3];
        }
    __syncthreads();

    float* __restrict__ ob = out + (size_t)b * NN * NN;
    const int rbase = ti * TILE;
    const int cbase = tj * TILE;

    for (int i2 = tid; i2 < 128 * 32; i2 += 128) {
        const int row = i2 >> 5;
        const int c4 = (i2 & 31) * 4;
        float4 v = make_float4(sf[row * 129 + c4], sf[row * 129 + c4 + 1],
                               sf[row * 129 + c4 + 2], sf[row * 129 + c4 + 3]);
        *(float4*)(ob + (size_t)(rbase + row) * NN + cbase + c4) = v;
    }
    if (!diag) {
        for (int i2 = tid; i2 < 128 * 32; i2 += 128) {
            const int mrow = i2 >> 5;
            const int c4 = (i2 & 31) * 4;
            float4 v = make_float4(sf[(c4 + 0) * 129 + mrow], sf[(c4 + 1) * 129 + mrow],
                                   sf[(c4 + 2) * 129 + mrow], sf[(c4 + 3) * 129 + mrow]);
            *(float4*)(ob + (size_t)(cbase + mrow) * NN + rbase + c4) = v;
        }
    }
}

// ---------------------------------------------------------------------------
// Kernel 2: per-row  t = (rowmax(e) - e) * adj;  out = softmax(t)
// ---------------------------------------------------------------------------
__device__ __forceinline__ float warp_max(float v) {
#pragma unroll
    for (int o = 16; o > 0; o >>= 1) v = fmaxf(v, __shfl_xor_sync(0xFFFFFFFFu, v, o));
    return v;
}
__device__ __forceinline__ float warp_sum(float v) {
#pragma unroll
    for (int o = 16; o > 0; o >>= 1) v += __shfl_xor_sync(0xFFFFFFFFu, v, o);
    return v;
}

__global__ __launch_bounds__(256, 8)
void softmax_adj_kernel(float* __restrict__ out, const float* __restrict__ adj) {
    const size_t row = blockIdx.x;
    float* __restrict__ e = out + row * NN;
    const float* __restrict__ a = adj + row * NN;

    __shared__ float red[8];
    const int tid = threadIdx.x, lane = tid & 31, wid = tid >> 5;

    float4 e0 = ((const float4*)e)[tid];
    float4 e1 = ((const float4*)e)[tid + 256];

    float m = fmaxf(fmaxf(fmaxf(e0.x, e0.y), fmaxf(e0.z, e0.w)),
                    fmaxf(fmaxf(e1.x, e1.y), fmaxf(e1.z, e1.w)));
    m = warp_max(m);
    if (lane == 0) red[wid] = m;
    __syncthreads();
    if (wid == 0) {
        float v = red[lane & 7];
        v = fmaxf(v, __shfl_xor_sync(0xFFFFFFFFu, v, 4));
        v = fmaxf(v, __shfl_xor_sync(0xFFFFFFFFu, v, 2));
        v = fmaxf(v, __shfl_xor_sync(0xFFFFFFFFu, v, 1));
        if (lane == 0) red[0] = v;
    }
    __syncthreads();
    const float M = red[0];
    __syncthreads();

    float4 a0 = ((const float4*)a)[tid];
    float4 a1 = ((const float4*)a)[tid + 256];

    float t[8];
    t[0] = (M - e0.x) * a0.x;  t[1] = (M - e0.y) * a0.y;
    t[2] = (M - e0.z) * a0.z;  t[3] = (M - e0.w) * a0.w;
    t[4] = (M - e1.x) * a1.x;  t[5] = (M - e1.y) * a1.y;
    t[6] = (M - e1.z) * a1.z;  t[7] = (M - e1.w) * a1.w;

    float tm = t[0];
#pragma unroll
    for (int k = 1; k < 8; k++) tm = fmaxf(tm, t[k]);
    tm = warp_max(tm);
    if (lane == 0) red[wid] = tm;
    __syncthreads();
    if (wid == 0) {
        float v = red[lane & 7];
        v = fmaxf(v, __shfl_xor_sync(0xFFFFFFFFu, v, 4));
        v = fmaxf(v, __shfl_xor_sync(0xFFFFFFFFu, v, 2));
        v = fmaxf(v, __shfl_xor_sync(0xFFFFFFFFu, v, 1));
        if (lane == 0) red[0] = v;
    }
    __syncthreads();
    const float T = red[0];
    __syncthreads();

    float p[8], s = 0.0f;
#pragma unroll
    for (int k = 0; k < 8; k++) { p[k] = __expf(t[k] - T); s += p[k]; }
    s = warp_sum(s);
    if (lane == 0) red[wid] = s;
    __syncthreads();
    if (wid == 0) {
        float v = red[lane & 7];
        v += __shfl_xor_sync(0xFFFFFFFFu, v, 4);
        v += __shfl_xor_sync(0xFFFFFFFFu, v, 2);
        v += __shfl_xor_sync(0xFFFFFFFFu, v, 1);
        if (lane == 0) red[0] = v;
    }
    __syncthreads();
    const float inv = 1.0f / red[0];

    ((float4*)e)[tid]       = make_float4(p[0] * inv, p[1] * inv, p[2] * inv, p[3] * inv);
    ((float4*)e)[tid + 256] = make_float4(p[4] * inv, p[5] * inv, p[6] * inv, p[7] * inv);
}

// ---------------------------------------------------------------------------
extern "C" void kernel_launch(void* const* d_in, const int* in_sizes, int n_in,
                              void* d_out, int out_size) {
    const float* h   = (const float*)d_in[0];   // [B, N, D]
    const float* adj = (const float*)d_in[1];   // [B, N, N]
    float* out = (float*)d_out;                 // [B, N, N]

    cudaFuncSetAttribute(energy_tc_kernel, cudaFuncAttributeMaxDynamicSharedMemorySize, SMEM_DYN);

    pack_a_kernel<<<2048, 256>>>(h);
    pack_b_kernel<<<4096, 256>>>(h);

    // phased: energy slice (33.6MB per 2 batches) stays L2-resident between
    // GEMM write and softmax read; softmax overwrites it in place so the
    // energy values never need to round-trip DRAM.
    for (int p = 0; p < BATCH / PHASE_B; p++) {
        const int b0 = p * PHASE_B;
        dim3 ggrid(NTRI, PHASE_B);
        energy_tc_kernel<<<ggrid, 128, SMEM_DYN>>>(out, b0);
        softmax_adj_kernel<<<PHASE_B * NN, 256>>>(out + (size_t)b0 * NN * NN,
                                                  adj + (size_t)b0 * NN * NN);
    }
}